// round 16
// baseline (speedup 1.0000x reference)
#include <cuda_runtime.h>
#include <cuda_bf16.h>
#include <mma.h>
#include <cstdint>
#include <cstddef>

using namespace nvcuda;

#define BATCH 64
#define SEQ   512
#define HID   1024
#define G4    4096
#define NCTA  128
#define OUT_ELEMS ((size_t)BATCH * SEQ * HID)

// Scratch (device globals — no allocation allowed).
static __device__ float g_xg[(size_t)SEQ * BATCH * G4];          // [t][b][g] (raw GEMM, no bias)
static __device__ float g_xa[(size_t)BATCH * SEQ * HID];         // tf32-rounded activations
static __device__ float g_wr[(size_t)HID * G4];                  // tf32-rounded W [k][n]
static __device__ __nv_bfloat16 g_hbuf[2][BATCH * HID];          // ping-pong hidden (bf16)
static __device__ unsigned g_bar;                                // grid barrier counter

__device__ __forceinline__ float sigm(float x) { return 1.0f / (1.0f + __expf(-x)); }

__device__ __forceinline__ void cpa16(uint32_t smem_dst, const void* gsrc) {
    asm volatile("cp.async.cg.shared.global [%0], [%1], 16;" :: "r"(smem_dst), "l"(gsrc));
}
__device__ __forceinline__ void cpa_commit() { asm volatile("cp.async.commit_group;"); }
__device__ __forceinline__ void cpa_wait0()  { asm volatile("cp.async.wait_group 0;" ::: "memory"); }

__device__ __forceinline__ float totf32(float x) {
    unsigned u;
    asm("cvt.rna.tf32.f32 %0, %1;" : "=r"(u) : "f"(x));
    return __uint_as_float(u);
}

// ---------------------------------------------------------------------------
// Pre-pass 1: elementwise tf32 rounding of activations -> g_xa (layer 0 only).
// ---------------------------------------------------------------------------
__global__ __launch_bounds__(256) void conv_a_kernel(const float* __restrict__ in) {
    size_t i = (size_t)blockIdx.x * 256 + threadIdx.x;
    float4 v = ((const float4*)in)[i];
    v.x = totf32(v.x); v.y = totf32(v.y); v.z = totf32(v.z); v.w = totf32(v.w);
    ((float4*)g_xa)[i] = v;
}

// ---------------------------------------------------------------------------
// Pre-pass 2: tf32 rounding of W [k][n] -> g_wr, PLUS per-layer state reset
// (g_bar and g_hbuf[0]) folded in — runs before every lstm launch.
// ---------------------------------------------------------------------------
__global__ __launch_bounds__(256) void conv_w_kernel(const float* __restrict__ W) {
    size_t i = (size_t)blockIdx.x * 256 + threadIdx.x;
    float4 v = ((const float4*)W)[i];
    v.x = totf32(v.x); v.y = totf32(v.y); v.z = totf32(v.z); v.w = totf32(v.w);
    ((float4*)g_wr)[i] = v;
    if (i == 0) g_bar = 0u;
    if (i < (BATCH * HID) / 2) ((uint32_t*)g_hbuf[0])[i] = 0u;   // 2 bf16 zeros
}

// ---------------------------------------------------------------------------
// wmma-tf32 projection v3: CTA tile 128(M) x 256(N), warp tile 64x64 (4x4
// frags). KC=64 double-buffered (16 chunks: half the syncs/waits of KC=32).
// NO bias, NO epilogue staging: fragments stored directly to g_xg with
// ldm = 64*4096. Bias is added inside lstm_seq_kernel. FP accumulation order
// identical to KC=32 (same serial K order per fragment chain).
// ---------------------------------------------------------------------------
#define PM 128
#define PN 256
#define PKC 64
#define SA_STR 72
#define SB_STR 260
#define PSTG (PM * SA_STR + PKC * SB_STR)        // 9216 + 16640 = 25856 floats
#define PJ_SMEM_BYTES (2 * PSTG * 4)             // 206848 B

__device__ __forceinline__ void proj_fill(uint32_t stg_u32,
                                          const float* __restrict__ a_r0,
                                          const float* __restrict__ w_c0,
                                          int k0, int tid) {
    uint32_t aB = stg_u32;
    uint32_t bB = stg_u32 + PM * SA_STR * 4;
#pragma unroll
    for (int i = 0; i < 8; i++) {          // A: 128 rows x 64 f32 = 2048 f4
        int u = tid + 256 * i;
        int r = u >> 4, f = u & 15;
        cpa16(aB + (r * SA_STR + f * 4) * 4, a_r0 + (size_t)r * HID + k0 + f * 4);
    }
#pragma unroll
    for (int i = 0; i < 16; i++) {         // B: 64 k-rows x 256 n = 4096 f4
        int u = tid + 256 * i;
        int k = u >> 6, f = u & 63;
        cpa16(bB + (k * SB_STR + f * 4) * 4, w_c0 + (size_t)(k0 + k) * G4 + f * 4);
    }
}

__global__ __launch_bounds__(256, 1) void proj_wmma_kernel() {
    extern __shared__ float ps[];

    const int tid = threadIdx.x;
    const int wid = tid >> 5;
    const int wm  = wid & 1;               // 2 warps along M (64 rows each)
    const int wn  = wid >> 1;              // 4 warps along N (64 cols each)

    const int col0 = blockIdx.x * PN;
    const int row0 = blockIdx.y * PM;

    const uint32_t ps_u32 = (uint32_t)__cvta_generic_to_shared(ps);
    const float* a_r0 = g_xa + (size_t)row0 * HID;
    const float* w_c0 = g_wr + col0;

    wmma::fragment<wmma::accumulator, 16, 16, 8, float> acc[4][4];
#pragma unroll
    for (int mt = 0; mt < 4; mt++)
#pragma unroll
        for (int nt = 0; nt < 4; nt++) wmma::fill_fragment(acc[mt][nt], 0.0f);

    proj_fill(ps_u32, a_r0, w_c0, 0, tid);
    cpa_commit();
    cpa_wait0();
    __syncthreads();

#pragma unroll 1
    for (int c = 0; c < HID / PKC; c++) {
        const int cs = c & 1, ns = cs ^ 1;
        const float* sA = ps + cs * PSTG;
        const float* sB = sA + PM * SA_STR;

        if (c < HID / PKC - 1) {
            proj_fill(ps_u32 + ns * PSTG * 4, a_r0, w_c0, (c + 1) * PKC, tid);
            cpa_commit();
        }

#pragma unroll
        for (int kt = 0; kt < 8; kt++) {
            wmma::fragment<wmma::matrix_a, 16, 16, 8, wmma::precision::tf32, wmma::row_major> af[4];
            wmma::fragment<wmma::matrix_b, 16, 16, 8, wmma::precision::tf32, wmma::row_major> bf[4];
#pragma unroll
            for (int mt = 0; mt < 4; mt++)
                wmma::load_matrix_sync(af[mt], sA + (wm * 64 + mt * 16) * SA_STR + kt * 8, SA_STR);
#pragma unroll
            for (int nt = 0; nt < 4; nt++)
                wmma::load_matrix_sync(bf[nt], sB + (kt * 8) * SB_STR + wn * 64 + nt * 16, SB_STR);
#pragma unroll
            for (int mt = 0; mt < 4; mt++)
#pragma unroll
                for (int nt = 0; nt < 4; nt++)
                    wmma::mma_sync(acc[mt][nt], af[mt], bf[nt], acc[mt][nt]);
        }

        cpa_wait0();
        __syncthreads();
    }

    // direct fragment->gmem store. Tile rows m = row0..row0+127 are one b,
    // s consecutive -> dst row stride = 64*4096 elements (constant).
    const int b  = row0 >> 9;
    const int s0 = row0 & (SEQ - 1);
    float* dst0 = g_xg + ((size_t)s0 * BATCH + b) * G4 + col0;
    const unsigned LDMG = BATCH * G4;      // 262144
#pragma unroll
    for (int mt = 0; mt < 4; mt++)
#pragma unroll
        for (int nt = 0; nt < 4; nt++)
            wmma::store_matrix_sync(dst0 + (size_t)(wm * 64 + mt * 16) * LDMG + wn * 64 + nt * 16,
                                    acc[mt][nt], LDMG, wmma::mem_row_major);
}

// ---------------------------------------------------------------------------
// Persistent recurrence kernel: R13-proven structure + two deltas:
//  (1) tid0-only device fence before the barrier atomic (PTX fence
//      cumulativity: syncthreads orders all threads' stores before tid0's
//      fence) — removes 15 warp-level MEMBAR.GPU per step.
//  (2) dead-store elimination: layer 0 writes g_xa only (proj2 input),
//      layer 1 writes hs only (final output).
// ---------------------------------------------------------------------------
#define SWS 40
#define SHS 1032
#define SGP 36
#define LS_WH_BYTES (HID * SWS * 2)                   // 81920
#define LS_H_BYTES  (64 * SHS * 2)                    // 132096
#define LS_SMEM_BYTES (LS_WH_BYTES + LS_H_BYTES)      // 214016

#define STEP_SUBQ(sq, waitn)                                                         \
    do {                                                                             \
        asm volatile("cp.async.wait_group " #waitn ";" ::: "memory");                \
        __syncwarp();                                                                \
        _Pragma("unroll")                                                            \
        for (int j = 0; j < 4; j++) {                                                \
            const int k16 = kgrp * 8 + (sq) * 4 + j;                                 \
            wmma::fragment<wmma::matrix_a, 16, 16, 16, __nv_bfloat16, wmma::row_major> a0, a1; \
            wmma::fragment<wmma::matrix_b, 16, 16, 16, __nv_bfloat16, wmma::row_major> b0, b1; \
            wmma::load_matrix_sync(a0, sH + (mhalf +  0) * SHS + k16 * 16, SHS);     \
            wmma::load_matrix_sync(a1, sH + (mhalf + 16) * SHS + k16 * 16, SHS);     \
            wmma::load_matrix_sync(b0, sWh + (k16 * 16) * SWS +  0, SWS);            \
            wmma::load_matrix_sync(b1, sWh + (k16 * 16) * SWS + 16, SWS);            \
            wmma::mma_sync(acc[0][0], a0, b0, acc[0][0]);                            \
            wmma::mma_sync(acc[0][1], a0, b1, acc[0][1]);                            \
            wmma::mma_sync(acc[1][0], a1, b0, acc[1][0]);                            \
            wmma::mma_sync(acc[1][1], a1, b1, acc[1][1]);                            \
        }                                                                            \
    } while (0)

__global__ __launch_bounds__(512, 1) void lstm_seq_kernel(const float* __restrict__ Wh,
                                                          const float* __restrict__ bx,
                                                          const float* __restrict__ bh,
                                                          float* __restrict__ hs,
                                                          float* __restrict__ hT,
                                                          float* __restrict__ cT,
                                                          int write_xa) {
    extern __shared__ char smc[];
    __nv_bfloat16* sWh = (__nv_bfloat16*)smc;                       // [1024][40]
    __nv_bfloat16* sH  = (__nv_bfloat16*)(smc + LS_WH_BYTES);       // [64][1032]
    float*         sGp = (float*)(smc + LS_WH_BYTES);               // overlay: [8][64][36]

    const int tid  = threadIdx.x;
    const int wid  = tid >> 5;
    const int lane = tid & 31;
    const int j0   = blockIdx.x * 8;

    // Wh slice fill, bf16-rounded (once per layer)
#pragma unroll 2
    for (int it = 0; it < 64; it++) {
        int idx = it * 512 + tid;
        int c = idx & 31, k = idx >> 5;
        int gcol = ((c >> 3) << 10) + j0 + (c & 7);
        sWh[k * SWS + c] = __float2bfloat16_rn(Wh[(size_t)k * G4 + gcol]);
    }

    const int kgrp  = wid >> 1;               // k-eighth this warp owns (0..7)
    const int mhalf = (wid & 1) * 32;         // M rows this warp owns
    const uint32_t sH_u32 = (uint32_t)__cvta_generic_to_shared(sH);

    // per-thread gate bias (bias moved out of the projection)
    const int bb = tid >> 3, jj = tid & 7;
    float bias[4];
#pragma unroll
    for (int g = 0; g < 4; g++) {
        int gcol = (g << 10) + j0 + jj;
        bias[g] = bx[gcol] + bh[gcol];
    }

    float creg = 0.0f;
    __syncthreads();

    unsigned target = NCTA;
    for (int t = 0; t < SEQ; t++) {
        const __nv_bfloat16* __restrict__ h_in = g_hbuf[t & 1];
        __nv_bfloat16* __restrict__ h_out      = g_hbuf[(t & 1) ^ 1];
        const float* __restrict__ xg_t = g_xg + (size_t)t * BATCH * G4;

        // warp-private fill: 32 rows x 128 k, as 2 sub-commits of 64 k each
#pragma unroll
        for (int sq = 0; sq < 2; sq++) {
#pragma unroll
            for (int i = 0; i < 8; i++) {
                int idx = i * 32 + lane;                  // 0..255
                int row = mhalf + (idx >> 3);
                int bcol = kgrp * 256 + sq * 128 + (idx & 7) * 16;   // bytes
                cpa16(sH_u32 + row * (SHS * 2) + bcol,
                      (const char*)h_in + (size_t)row * (HID * 2) + bcol);
            }
            cpa_commit();
        }

        // prefetch xg operands for the cell update (overlaps fill + GEMM)
        float xr[4];
#pragma unroll
        for (int g = 0; g < 4; g++)
            xr[g] = __ldg(&xg_t[(size_t)bb * G4 + (g << 10) + j0 + jj]);

        wmma::fragment<wmma::accumulator, 16, 16, 16, float> acc[2][2];
        wmma::fill_fragment(acc[0][0], 0.0f);
        wmma::fill_fragment(acc[0][1], 0.0f);
        wmma::fill_fragment(acc[1][0], 0.0f);
        wmma::fill_fragment(acc[1][1], 0.0f);

        // per-warp progressive pipeline: no CTA-wide syncs in the GEMM
        STEP_SUBQ(0, 1);
        STEP_SUBQ(1, 0);

        // all warps done reading sH -> safe to overlay partials onto it
        __syncthreads();
        {
            float* dst = sGp + kgrp * (64 * SGP);
#pragma unroll
            for (int mt = 0; mt < 2; mt++)
#pragma unroll
                for (int nt = 0; nt < 2; nt++)
                    wmma::store_matrix_sync(dst + (mhalf + mt * 16) * SGP + nt * 16,
                                            acc[mt][nt], SGP, wmma::mem_row_major);
        }
        __syncthreads();

        // cell update: sum 8 k-partials + xg + bias; c fp32 reg; h_out bf16.
        // Layer 0: g_xa (proj2 input). Layer 1: hs (final output).
        {
            int j = j0 + jj;
            float gi = xr[0] + bias[0], gf = xr[1] + bias[1];
            float gg = xr[2] + bias[2], go = xr[3] + bias[3];
#pragma unroll
            for (int g = 0; g < 8; g++) {
                const float* p = sGp + g * (64 * SGP) + bb * SGP;
                gi += p[jj];
                gf += p[8 + jj];
                gg += p[16 + jj];
                go += p[24 + jj];
            }
            float cn = sigm(gf) * creg + sigm(gi) * tanhf(gg);
            float hn = sigm(go) * tanhf(cn);
            creg = cn;
            h_out[bb * HID + j] = __float2bfloat16_rn(hn);
            if (write_xa)
                g_xa[((size_t)bb * SEQ + t) * HID + j] = totf32(hn);
            else
                hs[((size_t)bb * SEQ + t) * HID + j] = hn;
            if (t == SEQ - 1) {
                hT[bb * HID + j] = hn;
                cT[bb * HID + j] = cn;
            }
        }

        // device-wide barrier. tid0-only fence: __syncthreads orders all
        // threads' stores before tid0; the (cumulative) fence then makes them
        // device-visible before the barrier arrival.
        __syncthreads();
        if (tid == 0) {
            __threadfence();
            atomicAdd(&g_bar, 1u);
            int spins = 0;
            while (*(volatile unsigned*)&g_bar < target) {
                if (++spins > 8192) __nanosleep(64);
            }
        }
        __syncthreads();
        target += NCTA;
    }
}

// ---------------------------------------------------------------------------
extern "C" void kernel_launch(void* const* d_in, const int* in_sizes, int n_in,
                              void* d_out, int out_size) {
    (void)in_sizes; (void)n_in; (void)out_size;
    const float* x     = (const float*)d_in[0];
    const float* Wx[2] = {(const float*)d_in[1], (const float*)d_in[5]};
    const float* bx[2] = {(const float*)d_in[2], (const float*)d_in[6]};
    const float* Wh[2] = {(const float*)d_in[3], (const float*)d_in[7]};
    const float* bh[2] = {(const float*)d_in[4], (const float*)d_in[8]};

    float* out = (float*)d_out;
    float* hs  = out;                          // (B,S,H): final layer-1 output
    float* hT  = out + OUT_ELEMS;              // (L,B,H)
    float* cT  = hT + 2 * BATCH * HID;         // (L,B,H)

    static int attr_set = 0;
    if (!attr_set) {
        cudaFuncSetAttribute(lstm_seq_kernel, cudaFuncAttributeMaxDynamicSharedMemorySize,
                             LS_SMEM_BYTES);
        cudaFuncSetAttribute(proj_wmma_kernel, cudaFuncAttributeMaxDynamicSharedMemorySize,
                             PJ_SMEM_BYTES);
        attr_set = 1;
    }

    dim3 tgrid(G4 / PN, (BATCH * SEQ) / PM);   // (16, 256)

    for (int l = 0; l < 2; l++) {
        if (l == 0)
            conv_a_kernel<<<(int)(OUT_ELEMS / 1024), 256>>>(x);
        conv_w_kernel<<<(HID * G4) / 1024, 256>>>(Wx[l]);      // + g_bar/g_hbuf reset
        proj_wmma_kernel<<<tgrid, 256, PJ_SMEM_BYTES>>>();
        lstm_seq_kernel<<<NCTA, 512, LS_SMEM_BYTES>>>(
            Wh[l], bx[l], bh[l], hs, hT + l * BATCH * HID, cT + l * BATCH * HID,
            l == 0 ? 1 : 0);
    }
}

// round 17
// speedup vs baseline: 1.4713x; 1.4713x over previous
#include <cuda_runtime.h>
#include <cuda_bf16.h>
#include <mma.h>
#include <cstdint>
#include <cstddef>

using namespace nvcuda;

#define BATCH 64
#define SEQ   512
#define HID   1024
#define G4    4096
#define NCTA  128
#define OUT_ELEMS ((size_t)BATCH * SEQ * HID)

// Scratch (device globals — no allocation allowed).
static __device__ float g_xg[(size_t)SEQ * BATCH * G4];          // [t][b][g] (raw GEMM, no bias)
static __device__ float g_xa[(size_t)BATCH * SEQ * HID];         // tf32-rounded activations
static __device__ float g_wr[(size_t)HID * G4];                  // tf32-rounded W [k][n]
static __device__ __nv_bfloat16 g_hbuf[2][BATCH * HID];          // ping-pong hidden (bf16)
static __device__ unsigned g_bar;                                // grid barrier counter

__device__ __forceinline__ float sigm(float x) { return 1.0f / (1.0f + __expf(-x)); }

__device__ __forceinline__ void cpa16(uint32_t smem_dst, const void* gsrc) {
    asm volatile("cp.async.cg.shared.global [%0], [%1], 16;" :: "r"(smem_dst), "l"(gsrc));
}
__device__ __forceinline__ void cpa_commit() { asm volatile("cp.async.commit_group;"); }
__device__ __forceinline__ void cpa_wait0()  { asm volatile("cp.async.wait_group 0;" ::: "memory"); }
__device__ __forceinline__ void cpa_wait1()  { asm volatile("cp.async.wait_group 1;" ::: "memory"); }

__device__ __forceinline__ float totf32(float x) {
    unsigned u;
    asm("cvt.rna.tf32.f32 %0, %1;" : "=r"(u) : "f"(x));
    return __uint_as_float(u);
}

// ---------------------------------------------------------------------------
// Pre-pass 1: elementwise tf32 rounding of activations -> g_xa (layer 0 only).
// ---------------------------------------------------------------------------
__global__ __launch_bounds__(256) void conv_a_kernel(const float* __restrict__ in) {
    size_t i = (size_t)blockIdx.x * 256 + threadIdx.x;
    float4 v = ((const float4*)in)[i];
    v.x = totf32(v.x); v.y = totf32(v.y); v.z = totf32(v.z); v.w = totf32(v.w);
    ((float4*)g_xa)[i] = v;
}

// ---------------------------------------------------------------------------
// Pre-pass 2: tf32 rounding of W [k][n] -> g_wr, PLUS per-layer state reset
// (g_bar and g_hbuf[0]) folded in — runs before every lstm launch.
// ---------------------------------------------------------------------------
__global__ __launch_bounds__(256) void conv_w_kernel(const float* __restrict__ W) {
    size_t i = (size_t)blockIdx.x * 256 + threadIdx.x;
    float4 v = ((const float4*)W)[i];
    v.x = totf32(v.x); v.y = totf32(v.y); v.z = totf32(v.z); v.w = totf32(v.w);
    ((float4*)g_wr)[i] = v;
    if (i == 0) g_bar = 0u;
    if (i < (BATCH * HID) / 2) ((uint32_t*)g_hbuf[0])[i] = 0u;   // 2 bf16 zeros
}

// ---------------------------------------------------------------------------
// wmma-tf32 projection v4: CTA tile 128(M) x 256(N), warp tile 64x64 (4x4
// frags). KC=32, THREE-stage cp.async pipeline: wait only for chunk c
// (wait_group 1; chunk c+1 in flight), prefetch c+2, run MMA — the exposed
// end-of-chunk fill wait of the 2-stage version disappears. smem 155 KB.
// NO bias, NO epilogue staging (direct fragment->gmem, bias added in lstm).
// Accumulation order identical to v2 -> bit-identical results.
// ---------------------------------------------------------------------------
#define PM 128
#define PN 256
#define PKC 32
#define SA_STR 36
#define SB_STR 260
#define PSTG (PM * SA_STR + PKC * SB_STR)        // 4608 + 8320 = 12928 floats
#define PJ_SMEM_BYTES (3 * PSTG * 4)             // 155136 B

__device__ __forceinline__ void proj_fill(uint32_t stg_u32,
                                          const float* __restrict__ a_r0,
                                          const float* __restrict__ w_c0,
                                          int k0, int tid) {
    uint32_t aB = stg_u32;
    uint32_t bB = stg_u32 + PM * SA_STR * 4;
#pragma unroll
    for (int i = 0; i < 4; i++) {          // A: 128 rows x 32 f32 = 1024 f4
        int u = tid + 256 * i;
        int r = u >> 3, f = u & 7;
        cpa16(aB + (r * SA_STR + f * 4) * 4, a_r0 + (size_t)r * HID + k0 + f * 4);
    }
#pragma unroll
    for (int i = 0; i < 8; i++) {          // B: 32 k-rows x 256 n = 2048 f4
        int u = tid + 256 * i;
        int k = u >> 6, f = u & 63;
        cpa16(bB + (k * SB_STR + f * 4) * 4, w_c0 + (size_t)(k0 + k) * G4 + f * 4);
    }
}

__global__ __launch_bounds__(256, 1) void proj_wmma_kernel() {
    extern __shared__ float ps[];

    const int tid = threadIdx.x;
    const int wid = tid >> 5;
    const int wm  = wid & 1;               // 2 warps along M (64 rows each)
    const int wn  = wid >> 1;              // 4 warps along N (64 cols each)

    const int col0 = blockIdx.x * PN;
    const int row0 = blockIdx.y * PM;

    const uint32_t ps_u32 = (uint32_t)__cvta_generic_to_shared(ps);
    const float* a_r0 = g_xa + (size_t)row0 * HID;
    const float* w_c0 = g_wr + col0;

    wmma::fragment<wmma::accumulator, 16, 16, 8, float> acc[4][4];
#pragma unroll
    for (int mt = 0; mt < 4; mt++)
#pragma unroll
        for (int nt = 0; nt < 4; nt++) wmma::fill_fragment(acc[mt][nt], 0.0f);

    // prologue: chunks 0 and 1 in flight
    proj_fill(ps_u32, a_r0, w_c0, 0, tid);
    cpa_commit();
    proj_fill(ps_u32 + PSTG * 4, a_r0, w_c0, PKC, tid);
    cpa_commit();

    int buf = 0;                            // buffer index of chunk c (c mod 3)
#pragma unroll 1
    for (int c = 0; c < HID / PKC; c++) {
        // chunk c complete (c+1 may still be in flight); last chunk: drain all
        if (c == HID / PKC - 1) cpa_wait0(); else cpa_wait1();
        __syncthreads();

        if (c < HID / PKC - 2) {            // prefetch chunk c+2 into buf (c+2)%3
            int nb = buf + 2; if (nb >= 3) nb -= 3;
            proj_fill(ps_u32 + nb * PSTG * 4, a_r0, w_c0, (c + 2) * PKC, tid);
            cpa_commit();
        }

        const float* sA = ps + buf * PSTG;
        const float* sB = sA + PM * SA_STR;
#pragma unroll
        for (int kt = 0; kt < 4; kt++) {
            wmma::fragment<wmma::matrix_a, 16, 16, 8, wmma::precision::tf32, wmma::row_major> af[4];
            wmma::fragment<wmma::matrix_b, 16, 16, 8, wmma::precision::tf32, wmma::row_major> bf[4];
#pragma unroll
            for (int mt = 0; mt < 4; mt++)
                wmma::load_matrix_sync(af[mt], sA + (wm * 64 + mt * 16) * SA_STR + kt * 8, SA_STR);
#pragma unroll
            for (int nt = 0; nt < 4; nt++)
                wmma::load_matrix_sync(bf[nt], sB + (kt * 8) * SB_STR + wn * 64 + nt * 16, SB_STR);
#pragma unroll
            for (int mt = 0; mt < 4; mt++)
#pragma unroll
                for (int nt = 0; nt < 4; nt++)
                    wmma::mma_sync(acc[mt][nt], af[mt], bf[nt], acc[mt][nt]);
        }

        if (++buf == 3) buf = 0;
    }

    // direct fragment->gmem store. Tile rows m = row0..row0+127 are one b,
    // s consecutive -> dst row stride = 64*4096 elements (constant).
    const int b  = row0 >> 9;
    const int s0 = row0 & (SEQ - 1);
    float* dst0 = g_xg + ((size_t)s0 * BATCH + b) * G4 + col0;
    const unsigned LDMG = BATCH * G4;      // 262144
#pragma unroll
    for (int mt = 0; mt < 4; mt++)
#pragma unroll
        for (int nt = 0; nt < 4; nt++)
            wmma::store_matrix_sync(dst0 + (size_t)(wm * 64 + mt * 16) * LDMG + wn * 64 + nt * 16,
                                    acc[mt][nt], LDMG, wmma::mem_row_major);
}

// ---------------------------------------------------------------------------
// Persistent recurrence kernel: EXACT R15 version (proven 13.485 ms config):
// all-thread fence before the barrier (overlapped MEMBARs — the tid0-only
// variant regressed), bias added here, hs always written, g_xa when write_xa.
// ---------------------------------------------------------------------------
#define SWS 40
#define SHS 1032
#define SGP 36
#define LS_WH_BYTES (HID * SWS * 2)                   // 81920
#define LS_H_BYTES  (64 * SHS * 2)                    // 132096
#define LS_SMEM_BYTES (LS_WH_BYTES + LS_H_BYTES)      // 214016

#define STEP_SUBQ(sq, waitn)                                                         \
    do {                                                                             \
        asm volatile("cp.async.wait_group " #waitn ";" ::: "memory");                \
        __syncwarp();                                                                \
        _Pragma("unroll")                                                            \
        for (int j = 0; j < 4; j++) {                                                \
            const int k16 = kgrp * 8 + (sq) * 4 + j;                                 \
            wmma::fragment<wmma::matrix_a, 16, 16, 16, __nv_bfloat16, wmma::row_major> a0, a1; \
            wmma::fragment<wmma::matrix_b, 16, 16, 16, __nv_bfloat16, wmma::row_major> b0, b1; \
            wmma::load_matrix_sync(a0, sH + (mhalf +  0) * SHS + k16 * 16, SHS);     \
            wmma::load_matrix_sync(a1, sH + (mhalf + 16) * SHS + k16 * 16, SHS);     \
            wmma::load_matrix_sync(b0, sWh + (k16 * 16) * SWS +  0, SWS);            \
            wmma::load_matrix_sync(b1, sWh + (k16 * 16) * SWS + 16, SWS);            \
            wmma::mma_sync(acc[0][0], a0, b0, acc[0][0]);                            \
            wmma::mma_sync(acc[0][1], a0, b1, acc[0][1]);                            \
            wmma::mma_sync(acc[1][0], a1, b0, acc[1][0]);                            \
            wmma::mma_sync(acc[1][1], a1, b1, acc[1][1]);                            \
        }                                                                            \
    } while (0)

__global__ __launch_bounds__(512, 1) void lstm_seq_kernel(const float* __restrict__ Wh,
                                                          const float* __restrict__ bx,
                                                          const float* __restrict__ bh,
                                                          float* __restrict__ hs,
                                                          float* __restrict__ hT,
                                                          float* __restrict__ cT,
                                                          int write_xa) {
    extern __shared__ char smc[];
    __nv_bfloat16* sWh = (__nv_bfloat16*)smc;                       // [1024][40]
    __nv_bfloat16* sH  = (__nv_bfloat16*)(smc + LS_WH_BYTES);       // [64][1032]
    float*         sGp = (float*)(smc + LS_WH_BYTES);               // overlay: [8][64][36]

    const int tid  = threadIdx.x;
    const int wid  = tid >> 5;
    const int lane = tid & 31;
    const int j0   = blockIdx.x * 8;

    // Wh slice fill, bf16-rounded (once per layer)
#pragma unroll 2
    for (int it = 0; it < 64; it++) {
        int idx = it * 512 + tid;
        int c = idx & 31, k = idx >> 5;
        int gcol = ((c >> 3) << 10) + j0 + (c & 7);
        sWh[k * SWS + c] = __float2bfloat16_rn(Wh[(size_t)k * G4 + gcol]);
    }

    const int kgrp  = wid >> 1;               // k-eighth this warp owns (0..7)
    const int mhalf = (wid & 1) * 32;         // M rows this warp owns
    const uint32_t sH_u32 = (uint32_t)__cvta_generic_to_shared(sH);

    // per-thread gate bias (bias moved out of the projection)
    const int bb = tid >> 3, jj = tid & 7;
    float bias[4];
#pragma unroll
    for (int g = 0; g < 4; g++) {
        int gcol = (g << 10) + j0 + jj;
        bias[g] = bx[gcol] + bh[gcol];
    }

    float creg = 0.0f;
    __syncthreads();

    unsigned target = NCTA;
    for (int t = 0; t < SEQ; t++) {
        const __nv_bfloat16* __restrict__ h_in = g_hbuf[t & 1];
        __nv_bfloat16* __restrict__ h_out      = g_hbuf[(t & 1) ^ 1];
        const float* __restrict__ xg_t = g_xg + (size_t)t * BATCH * G4;

        // warp-private fill: 32 rows x 128 k, as 2 sub-commits of 64 k each
#pragma unroll
        for (int sq = 0; sq < 2; sq++) {
#pragma unroll
            for (int i = 0; i < 8; i++) {
                int idx = i * 32 + lane;                  // 0..255
                int row = mhalf + (idx >> 3);
                int bcol = kgrp * 256 + sq * 128 + (idx & 7) * 16;   // bytes
                cpa16(sH_u32 + row * (SHS * 2) + bcol,
                      (const char*)h_in + (size_t)row * (HID * 2) + bcol);
            }
            cpa_commit();
        }

        // prefetch xg operands for the cell update (overlaps fill + GEMM)
        float xr[4];
#pragma unroll
        for (int g = 0; g < 4; g++)
            xr[g] = __ldg(&xg_t[(size_t)bb * G4 + (g << 10) + j0 + jj]);

        wmma::fragment<wmma::accumulator, 16, 16, 16, float> acc[2][2];
        wmma::fill_fragment(acc[0][0], 0.0f);
        wmma::fill_fragment(acc[0][1], 0.0f);
        wmma::fill_fragment(acc[1][0], 0.0f);
        wmma::fill_fragment(acc[1][1], 0.0f);

        // per-warp progressive pipeline: no CTA-wide syncs in the GEMM
        STEP_SUBQ(0, 1);
        STEP_SUBQ(1, 0);

        // all warps done reading sH -> safe to overlay partials onto it
        __syncthreads();
        {
            float* dst = sGp + kgrp * (64 * SGP);
#pragma unroll
            for (int mt = 0; mt < 2; mt++)
#pragma unroll
                for (int nt = 0; nt < 2; nt++)
                    wmma::store_matrix_sync(dst + (mhalf + mt * 16) * SGP + nt * 16,
                                            acc[mt][nt], SGP, wmma::mem_row_major);
        }
        __syncthreads();

        // cell update: sum 8 k-partials + xg + bias; c fp32 reg; h_out bf16;
        // hs fp32; g_xa tf32 (only when a next layer consumes it)
        {
            int j = j0 + jj;
            float gi = xr[0] + bias[0], gf = xr[1] + bias[1];
            float gg = xr[2] + bias[2], go = xr[3] + bias[3];
#pragma unroll
            for (int g = 0; g < 8; g++) {
                const float* p = sGp + g * (64 * SGP) + bb * SGP;
                gi += p[jj];
                gf += p[8 + jj];
                gg += p[16 + jj];
                go += p[24 + jj];
            }
            float cn = sigm(gf) * creg + sigm(gi) * tanhf(gg);
            float hn = sigm(go) * tanhf(cn);
            creg = cn;
            h_out[bb * HID + j] = __float2bfloat16_rn(hn);
            hs[((size_t)bb * SEQ + t) * HID + j] = hn;
            if (write_xa)
                g_xa[((size_t)bb * SEQ + t) * HID + j] = totf32(hn);
            if (t == SEQ - 1) {
                hT[bb * HID + j] = hn;
                cT[bb * HID + j] = cn;
            }
        }

        // device-wide barrier: all-thread fence (overlapped MEMBARs), then
        // tid0 arrives + spins. (tid0-only fence variant measured SLOWER.)
        __threadfence();
        __syncthreads();
        if (tid == 0) {
            atomicAdd(&g_bar, 1u);
            int spins = 0;
            while (*(volatile unsigned*)&g_bar < target) {
                if (++spins > 8192) __nanosleep(64);
            }
        }
        __syncthreads();
        target += NCTA;
    }
}

// ---------------------------------------------------------------------------
extern "C" void kernel_launch(void* const* d_in, const int* in_sizes, int n_in,
                              void* d_out, int out_size) {
    (void)in_sizes; (void)n_in; (void)out_size;
    const float* x     = (const float*)d_in[0];
    const float* Wx[2] = {(const float*)d_in[1], (const float*)d_in[5]};
    const float* bx[2] = {(const float*)d_in[2], (const float*)d_in[6]};
    const float* Wh[2] = {(const float*)d_in[3], (const float*)d_in[7]};
    const float* bh[2] = {(const float*)d_in[4], (const float*)d_in[8]};

    float* out = (float*)d_out;
    float* hs  = out;                          // (B,S,H): layer0 scratch, then final layer1 output
    float* hT  = out + OUT_ELEMS;              // (L,B,H)
    float* cT  = hT + 2 * BATCH * HID;         // (L,B,H)

    static int attr_set = 0;
    if (!attr_set) {
        cudaFuncSetAttribute(lstm_seq_kernel, cudaFuncAttributeMaxDynamicSharedMemorySize,
                             LS_SMEM_BYTES);
        cudaFuncSetAttribute(proj_wmma_kernel, cudaFuncAttributeMaxDynamicSharedMemorySize,
                             PJ_SMEM_BYTES);
        attr_set = 1;
    }

    dim3 tgrid(G4 / PN, (BATCH * SEQ) / PM);   // (16, 256)

    for (int l = 0; l < 2; l++) {
        if (l == 0)
            conv_a_kernel<<<(int)(OUT_ELEMS / 1024), 256>>>(x);
        conv_w_kernel<<<(HID * G4) / 1024, 256>>>(Wx[l]);      // + g_bar/g_hbuf reset
        proj_wmma_kernel<<<tgrid, 256, PJ_SMEM_BYTES>>>();
        lstm_seq_kernel<<<NCTA, 512, LS_SMEM_BYTES>>>(
            Wh[l], bx[l], bh[l], hs, hT + l * BATCH * HID, cT + l * BATCH * HID,
            l == 0 ? 1 : 0);
    }
}